// round 14
// baseline (speedup 1.0000x reference)
#include <cuda_runtime.h>
#include <cuda_fp16.h>
#include <math.h>
#include <stdint.h>

#define BATCH 1024
#define TSEQ  256
#define CDIM  384
#define HDIM  64
#define NDIM  192
#define KC    64

// ---- global scratch: pre-swizzled fp16 W ------------------------------------
__device__ __align__(16) __half gW[CDIM * NDIM];

// ---- helpers ----------------------------------------------------------------
__device__ __forceinline__ uint32_t smem_u32(const void* p) {
    uint32_t a;
    asm("{ .reg .u64 t; cvta.to.shared.u64 t, %1; cvt.u32.u64 %0, t; }" : "=r"(a) : "l"(p));
    return a;
}
// 128B-row tile swizzle (8 16B atoms per row)
__device__ __forceinline__ int swz128(int row, int byteoff) {
    return row * 128 + ((((byteoff >> 4) ^ row) & 7) << 4) + (byteoff & 15);
}
// W tile: 384B rows (24 atoms), swizzle within 8-atom groups
__device__ __forceinline__ int swzW(int k, int byteoff) {
    int atom = byteoff >> 4;
    return k * 384 + (((atom & ~7) | ((atom ^ k) & 7)) << 4) + (byteoff & 15);
}
__device__ __forceinline__ uint32_t pkh(float lo, float hi) {   // f16x2 {hi|lo}
    uint32_t r; asm("cvt.rn.f16x2.f32 %0, %1, %2;" : "=r"(r) : "f"(hi), "f"(lo)); return r;
}
__device__ __forceinline__ float ex2(float x) {
    float y; asm("ex2.approx.ftz.f32 %0, %1;" : "=f"(y) : "f"(x)); return y;
}
__device__ __forceinline__ void ldsm4(uint32_t* r, uint32_t a) {
    asm volatile("ldmatrix.sync.aligned.m8n8.x4.shared.b16 {%0,%1,%2,%3}, [%4];"
                 : "=r"(r[0]), "=r"(r[1]), "=r"(r[2]), "=r"(r[3]) : "r"(a));
}
__device__ __forceinline__ void ldsm4t(uint32_t* r, uint32_t a) {
    asm volatile("ldmatrix.sync.aligned.m8n8.x4.trans.shared.b16 {%0,%1,%2,%3}, [%4];"
                 : "=r"(r[0]), "=r"(r[1]), "=r"(r[2]), "=r"(r[3]) : "r"(a));
}
__device__ __forceinline__ void ldsm2(uint32_t& r0, uint32_t& r1, uint32_t a) {
    asm volatile("ldmatrix.sync.aligned.m8n8.x2.shared.b16 {%0,%1}, [%2];"
                 : "=r"(r0), "=r"(r1) : "r"(a));
}
__device__ __forceinline__ void ldsm2t(uint32_t& r0, uint32_t& r1, uint32_t a) {
    asm volatile("ldmatrix.sync.aligned.m8n8.x2.trans.shared.b16 {%0,%1}, [%2];"
                 : "=r"(r0), "=r"(r1) : "r"(a));
}
__device__ __forceinline__ void mma16816(float* c, const uint32_t* a,
                                         uint32_t b0, uint32_t b1) {
    asm volatile("mma.sync.aligned.m16n8k16.row.col.f32.f16.f16.f32 "
                 "{%0,%1,%2,%3}, {%4,%5,%6,%7}, {%8,%9}, {%0,%1,%2,%3};"
                 : "+f"(c[0]), "+f"(c[1]), "+f"(c[2]), "+f"(c[3])
                 : "r"(a[0]), "r"(a[1]), "r"(a[2]), "r"(a[3]), "r"(b0), "r"(b1));
}

// ============================================================================
// Kernel 0: pre-convert W -> fp16, pre-swizzled [384k x 192n] layout.
// ============================================================================
__global__ void prep_w(const float* __restrict__ Wq, const float* __restrict__ Wk,
                       const float* __restrict__ Wv) {
    int idx = blockIdx.x * 256 + threadIdx.x;      // over 384*192
    if (idx >= CDIM * NDIM) return;
    int k = idx / NDIM, n = idx % NDIM;
    const float* Wp = (n < 64) ? Wq : (n < 128) ? Wk : Wv;
    float v = Wp[k * HDIM + (n & 63)];
    *reinterpret_cast<__half*>(reinterpret_cast<char*>(gW) + swzW(k, 2 * n)) =
        __float2half_rn(v);
}

// ============================================================================
// Fused kernel: QKV projection (2 half-passes) + causal flash attention
// with diagonal-tile MAC skipping.
// ============================================================================
#define FQ 0
#define FK 32768
#define FV 65536
#define FX(buf) (98304  + (buf) * 16384)
#define FW(buf) (131072 + (buf) * 24576)
#define FSMEM 180224

__global__ void __launch_bounds__(256, 1)
head_kernel(const float* __restrict__ x, float* __restrict__ out)
{
    extern __shared__ char sm[];
    const uint32_t smb = smem_u32(sm);
    const int tid = threadIdx.x, lane = tid & 31, w = tid >> 5;
    const int wm = w & 3, wn = w >> 2;
    const int g = lane >> 2, t2 = (lane & 3) << 1;
    const char* gw = reinterpret_cast<const char*>(gW);
    const float eta = 1.44269504088896340736f * rsqrtf((float)CDIM);

    // ===================== Phase 1: QKV -> smem (2 half-passes) ==============
    for (int half = 0; half < 2; ++half) {
        const int rhalf = half << 7;
        const float* gx = x + ((size_t)blockIdx.x * TSEQ + rhalf) * CDIM;

        float acc[2][12][4];
#pragma unroll
        for (int mt = 0; mt < 2; ++mt)
#pragma unroll
            for (int nt = 0; nt < 12; ++nt)
#pragma unroll
                for (int i = 0; i < 4; ++i) acc[mt][nt][i] = 0.f;

        float4 xp[8];
#pragma unroll
        for (int i = 0; i < 8; ++i) {
            int idx = tid + (i << 8);
            xp[i] = *reinterpret_cast<const float4*>(
                gx + (idx >> 4) * CDIM + ((idx & 15) << 2));
        }

        for (int ch = 0; ch < 6; ++ch) {
            const int buf = ch & 1;
#pragma unroll
            for (int i = 0; i < 8; ++i) {
                int idx = tid + (i << 8);
                int row = idx >> 4, f4 = idx & 15;
                float4 v = xp[i];
                *reinterpret_cast<uint2*>(sm + FX(buf) + swz128(row, f4 << 3)) =
                    make_uint2(pkh(v.x, v.y), pkh(v.z, v.w));
            }
            {
                const int slab = ch * 24576;
#pragma unroll
                for (int i = 0; i < 6; ++i) {
                    int boff = (tid + (i << 8)) << 4;
                    *reinterpret_cast<uint4*>(sm + FW(buf) + boff) =
                        *reinterpret_cast<const uint4*>(gw + slab + boff);
                }
            }
            __syncthreads();
            if (ch < 5) {
                const int kc = (ch + 1) * KC;
#pragma unroll
                for (int i = 0; i < 8; ++i) {
                    int idx = tid + (i << 8);
                    xp[i] = *reinterpret_cast<const float4*>(
                        gx + (idx >> 4) * CDIM + kc + ((idx & 15) << 2));
                }
            }
#pragma unroll
            for (int ks = 0; ks < 4; ++ks) {
                uint32_t ah[2][4];
                int arow  = (wm << 5) + (lane & 15);
                int abyte = ((ks << 1) + (lane >> 4)) << 4;
                ldsm4(ah[0], smb + FX(buf) + swz128(arow,      abyte));
                ldsm4(ah[1], smb + FX(buf) + swz128(arow + 16, abyte));
                int krow = (ks << 4) + (lane & 15);
#pragma unroll
                for (int j = 0; j < 6; ++j) {
                    const int n0 = 2 * j;
                    const int ntg = wn * 12 + n0;
                    uint32_t bh[4];
                    ldsm4t(bh, smb + FW(buf) + swzW(krow, (ntg + (lane >> 4)) << 4));
                    mma16816(acc[0][n0],     ah[0], bh[0], bh[1]);
                    mma16816(acc[1][n0],     ah[1], bh[0], bh[1]);
                    mma16816(acc[0][n0 + 1], ah[0], bh[2], bh[3]);
                    mma16816(acc[1][n0 + 1], ah[1], bh[2], bh[3]);
                }
            }
        }

#pragma unroll
        for (int mt = 0; mt < 2; ++mt) {
#pragma unroll
            for (int ntl = 0; ntl < 12; ++ntl) {
                const int ntg = wn * 12 + ntl;
#pragma unroll
                for (int r = 0; r < 2; ++r) {
                    float p0 = acc[mt][ntl][2 * r], p1 = acc[mt][ntl][2 * r + 1];
                    if (ntg < 8) { p0 *= eta; p1 *= eta; }
                    int row = rhalf + (wm << 5) + (mt << 4) + g + (r << 3);
                    int sec = ntg >> 3;
                    int off = swz128(row, ((ntg & 7) << 4) + (t2 << 1));
                    *reinterpret_cast<uint32_t*>(sm + sec * 32768 + off) = pkh(p0, p1);
                }
            }
        }
    }
    __syncthreads();

    // ===================== Phase 2: balanced causal flash attention ==========
    const int b0 = w, b1 = 15 - w;
    const int rbase0 = b0 << 4,  rbase1 = b1 << 4;
    const int jmax0  = b0 >> 2,  jmax1  = b1 >> 2;        // jmax1 >= jmax0
    // diagonal-tile bounds: needed cols < 16*(b&3)+16
    const int ntmax0 = 2 * (b0 & 3) + 2, ntmax1 = 2 * (b1 & 3) + 2;   // of 8
    const int ksmax0 = (b0 & 3) + 1,     ksmax1 = (b1 & 3) + 1;       // of 4

    float O[2][8][4];
#pragma unroll
    for (int mt = 0; mt < 2; ++mt)
#pragma unroll
        for (int nt = 0; nt < 8; ++nt)
#pragma unroll
            for (int i = 0; i < 4; ++i) O[mt][nt][i] = 0.f;
    float mrow[2][2] = {{-1e30f, -1e30f}, {-1e30f, -1e30f}};
    float lrow[2][2] = {{0.f, 0.f}, {0.f, 0.f}};

    for (int jt = 0; jt <= jmax1; ++jt) {
        const bool act0  = (jt <= jmax0);
        const bool diag0 = (jt == jmax0);
        const bool diag1 = (jt == jmax1);
        float S[2][8][4];
#pragma unroll
        for (int mt = 0; mt < 2; ++mt)
#pragma unroll
            for (int nt = 0; nt < 8; ++nt)
#pragma unroll
                for (int i = 0; i < 4; ++i) S[mt][nt][i] = 0.f;

        // ---- S = Q K^T (skip fully-masked n-tiles on diagonal tiles) ----------
#pragma unroll
        for (int ks = 0; ks < 4; ++ks) {
            uint32_t qh[2][4];
            int abyte = ((ks << 1) + (lane >> 4)) << 4;
            int lrow16 = lane & 15;
            if (act0) ldsm4(qh[0], smb + FQ + swz128(rbase0 + lrow16, abyte));
            ldsm4(qh[1], smb + FQ + swz128(rbase1 + lrow16, abyte));
            int kr    = (jt << 6) + (lane & 7);
            int kbyte = ((ks << 1) + ((lane >> 3) & 1)) << 4;
#pragma unroll
            for (int nt = 0; nt < 8; ++nt) {
                const bool need0 = act0 && (!diag0 || nt < ntmax0);
                const bool need1 = (!diag1 || nt < ntmax1);
                if (need0 || need1) {
                    uint32_t c0, c1;
                    ldsm2(c0, c1, smb + FK + swz128(kr + (nt << 3), kbyte));
                    if (need0) mma16816(S[0][nt], qh[0], c0, c1);
                    if (need1) mma16816(S[1][nt], qh[1], c0, c1);
                }
            }
        }
        // ---- causal mask on each block's diagonal tile --------------------------
#pragma unroll
        for (int mt = 0; mt < 2; ++mt) {
            const int jm = (mt == 0) ? jmax0 : jmax1;
            const int rb = (mt == 0) ? rbase0 : rbase1;
            if (jt == jm) {
#pragma unroll
                for (int nt = 0; nt < 8; ++nt)
#pragma unroll
                    for (int r = 0; r < 2; ++r)
#pragma unroll
                        for (int cc = 0; cc < 2; ++cc) {
                            int col = (jt << 6) + (nt << 3) + t2 + cc;
                            int row = rb + g + (r << 3);
                            if (col > row) S[mt][nt][2 * r + cc] = -1e30f;
                        }
            }
        }
        // ---- online softmax (active blocks only; guarded O-rescale) -------------
#pragma unroll
        for (int mt = 0; mt < 2; ++mt) {
            if (mt == 0 && !act0) continue;
#pragma unroll
            for (int r = 0; r < 2; ++r) {
                float vmax = -1e30f;
#pragma unroll
                for (int nt = 0; nt < 8; ++nt)
                    vmax = fmaxf(vmax, fmaxf(S[mt][nt][2 * r], S[mt][nt][2 * r + 1]));
                vmax = fmaxf(vmax, __shfl_xor_sync(0xffffffffu, vmax, 1));
                vmax = fmaxf(vmax, __shfl_xor_sync(0xffffffffu, vmax, 2));
                float mnew  = fmaxf(mrow[mt][r], vmax);
                float alpha = ex2(mrow[mt][r] - mnew);
                mrow[mt][r] = mnew;
                float ls = 0.f;
#pragma unroll
                for (int nt = 0; nt < 8; ++nt) {
                    float p0 = ex2(S[mt][nt][2 * r]     - mnew);
                    float p1 = ex2(S[mt][nt][2 * r + 1] - mnew);
                    S[mt][nt][2 * r] = p0; S[mt][nt][2 * r + 1] = p1;
                    ls += p0 + p1;
                }
                lrow[mt][r] = lrow[mt][r] * alpha + ls;
                if (alpha != 1.f) {
#pragma unroll
                    for (int nt = 0; nt < 8; ++nt) {
                        O[mt][nt][2 * r]     *= alpha;
                        O[mt][nt][2 * r + 1] *= alpha;
                    }
                }
            }
        }
        // ---- O += P V (skip exact-zero ks-steps on diagonal tiles) ---------------
#pragma unroll
        for (int ks = 0; ks < 4; ++ks) {
            const bool p0 = act0 && (!diag0 || ks < ksmax0);
            const bool p1 = (!diag1 || ks < ksmax1);
            if (!(p0 || p1)) continue;
            uint32_t ph[2][4];
#pragma unroll
            for (int mt = 0; mt < 2; ++mt) {
                if ((mt == 0 && !p0) || (mt == 1 && !p1)) continue;
                ph[mt][0] = pkh(S[mt][2 * ks][0],     S[mt][2 * ks][1]);
                ph[mt][1] = pkh(S[mt][2 * ks][2],     S[mt][2 * ks][3]);
                ph[mt][2] = pkh(S[mt][2 * ks + 1][0], S[mt][2 * ks + 1][1]);
                ph[mt][3] = pkh(S[mt][2 * ks + 1][2], S[mt][2 * ks + 1][3]);
            }
            int vr = (jt << 6) + (ks << 4) + (lane & 15);
#pragma unroll
            for (int nt = 0; nt < 8; ++nt) {
                uint32_t c0, c1;
                ldsm2t(c0, c1, smb + FV + swz128(vr, nt << 4));
                if (p0) mma16816(O[0][nt], ph[0], c0, c1);
                if (p1) mma16816(O[1][nt], ph[1], c0, c1);
            }
        }
    }

    // ---- finalize + store --------------------------------------------------------
#pragma unroll
    for (int mt = 0; mt < 2; ++mt) {
        const int rb = (mt == 0) ? rbase0 : rbase1;
#pragma unroll
        for (int r = 0; r < 2; ++r) {
            float lt = lrow[mt][r];
            lt += __shfl_xor_sync(0xffffffffu, lt, 1);
            lt += __shfl_xor_sync(0xffffffffu, lt, 2);
            float inv = __frcp_rn(lt);
            int row = rb + g + (r << 3);
            float* op = out + ((size_t)blockIdx.x * TSEQ + row) * HDIM;
#pragma unroll
            for (int nt = 0; nt < 8; ++nt) {
                float2 v = make_float2(O[mt][nt][2 * r] * inv, O[mt][nt][2 * r + 1] * inv);
                *reinterpret_cast<float2*>(op + (nt << 3) + t2) = v;
            }
        }
    }
}

// ---- launch -----------------------------------------------------------------
extern "C" void kernel_launch(void* const* d_in, const int* in_sizes, int n_in,
                              void* d_out, int out_size)
{
    const float* x  = (const float*)d_in[0];
    const float* Wq = (const float*)d_in[1];
    const float* Wk = (const float*)d_in[2];
    const float* Wv = (const float*)d_in[3];
    float* out = (float*)d_out;

    int B = in_sizes[0] / (TSEQ * CDIM);          // 1024

    cudaFuncSetAttribute(head_kernel, cudaFuncAttributeMaxDynamicSharedMemorySize, FSMEM);

    prep_w<<<(CDIM * NDIM + 255) / 256, 256>>>(Wq, Wk, Wv);
    head_kernel<<<B, 256, FSMEM>>>(x, out);
}

// round 15
// speedup vs baseline: 1.0981x; 1.0981x over previous
#include <cuda_runtime.h>
#include <cuda_fp16.h>
#include <math.h>
#include <stdint.h>

#define BATCH 1024
#define TSEQ  256
#define CDIM  384
#define HDIM  64
#define NDIM  192
#define KC    64

// ---- global scratch: pre-swizzled fp16 W ------------------------------------
__device__ __align__(16) __half gW[CDIM * NDIM];

// ---- helpers ----------------------------------------------------------------
__device__ __forceinline__ uint32_t smem_u32(const void* p) {
    uint32_t a;
    asm("{ .reg .u64 t; cvta.to.shared.u64 t, %1; cvt.u32.u64 %0, t; }" : "=r"(a) : "l"(p));
    return a;
}
// 128B-row tile swizzle (8 16B atoms per row)
__device__ __forceinline__ int swz128(int row, int byteoff) {
    return row * 128 + ((((byteoff >> 4) ^ row) & 7) << 4) + (byteoff & 15);
}
// W tile: 384B rows (24 atoms), swizzle within 8-atom groups
__device__ __forceinline__ int swzW(int k, int byteoff) {
    int atom = byteoff >> 4;
    return k * 384 + (((atom & ~7) | ((atom ^ k) & 7)) << 4) + (byteoff & 15);
}
__device__ __forceinline__ uint32_t pkh(float lo, float hi) {   // f16x2 {hi|lo}
    uint32_t r; asm("cvt.rn.f16x2.f32 %0, %1, %2;" : "=r"(r) : "f"(hi), "f"(lo)); return r;
}
__device__ __forceinline__ float ex2(float x) {
    float y; asm("ex2.approx.ftz.f32 %0, %1;" : "=f"(y) : "f"(x)); return y;
}
__device__ __forceinline__ void ldsm4(uint32_t* r, uint32_t a) {
    asm volatile("ldmatrix.sync.aligned.m8n8.x4.shared.b16 {%0,%1,%2,%3}, [%4];"
                 : "=r"(r[0]), "=r"(r[1]), "=r"(r[2]), "=r"(r[3]) : "r"(a));
}
__device__ __forceinline__ void ldsm4t(uint32_t* r, uint32_t a) {
    asm volatile("ldmatrix.sync.aligned.m8n8.x4.trans.shared.b16 {%0,%1,%2,%3}, [%4];"
                 : "=r"(r[0]), "=r"(r[1]), "=r"(r[2]), "=r"(r[3]) : "r"(a));
}
__device__ __forceinline__ void ldsm2(uint32_t& r0, uint32_t& r1, uint32_t a) {
    asm volatile("ldmatrix.sync.aligned.m8n8.x2.shared.b16 {%0,%1}, [%2];"
                 : "=r"(r0), "=r"(r1) : "r"(a));
}
__device__ __forceinline__ void ldsm2t(uint32_t& r0, uint32_t& r1, uint32_t a) {
    asm volatile("ldmatrix.sync.aligned.m8n8.x2.trans.shared.b16 {%0,%1}, [%2];"
                 : "=r"(r0), "=r"(r1) : "r"(a));
}
__device__ __forceinline__ void mma16816(float* c, const uint32_t* a,
                                         uint32_t b0, uint32_t b1) {
    asm volatile("mma.sync.aligned.m16n8k16.row.col.f32.f16.f16.f32 "
                 "{%0,%1,%2,%3}, {%4,%5,%6,%7}, {%8,%9}, {%0,%1,%2,%3};"
                 : "+f"(c[0]), "+f"(c[1]), "+f"(c[2]), "+f"(c[3])
                 : "r"(a[0]), "r"(a[1]), "r"(a[2]), "r"(a[3]), "r"(b0), "r"(b1));
}

// ============================================================================
// Kernel 0: pre-convert W -> fp16, pre-swizzled [384k x 192n] layout.
// ============================================================================
__global__ void prep_w(const float* __restrict__ Wq, const float* __restrict__ Wk,
                       const float* __restrict__ Wv) {
    int idx = blockIdx.x * 256 + threadIdx.x;      // over 384*192
    if (idx >= CDIM * NDIM) return;
    int k = idx / NDIM, n = idx % NDIM;
    const float* Wp = (n < 64) ? Wq : (n < 128) ? Wk : Wv;
    float v = Wp[k * HDIM + (n & 63)];
    *reinterpret_cast<__half*>(reinterpret_cast<char*>(gW) + swzW(k, 2 * n)) =
        __float2half_rn(v);
}

// ============================================================================
// Fused kernel: QKV projection (2 half-passes) + causal flash attention.
// grid = 1024 (one CTA per batch), 256 thr.
// smem: Q 32KB | K 32KB | V 32KB | X dbuf 2x16KB | W dbuf 2x24KB = 176KB
// ============================================================================
#define FQ 0
#define FK 32768
#define FV 65536
#define FX(buf) (98304  + (buf) * 16384)
#define FW(buf) (131072 + (buf) * 24576)
#define FSMEM 180224

__global__ void __launch_bounds__(256, 1)
head_kernel(const float* __restrict__ x, float* __restrict__ out)
{
    extern __shared__ char sm[];
    const uint32_t smb = smem_u32(sm);
    const int tid = threadIdx.x, lane = tid & 31, w = tid >> 5;
    const int wm = w & 3, wn = w >> 2;
    const int g = lane >> 2, t2 = (lane & 3) << 1;
    const char* gw = reinterpret_cast<const char*>(gW);
    const float eta = 1.44269504088896340736f * rsqrtf((float)CDIM);

    // ===================== Phase 1: QKV -> smem (2 half-passes) ==============
    for (int half = 0; half < 2; ++half) {
        const int rhalf = half << 7;                       // 0 or 128
        const float* gx = x + ((size_t)blockIdx.x * TSEQ + rhalf) * CDIM;

        float acc[2][12][4];
#pragma unroll
        for (int mt = 0; mt < 2; ++mt)
#pragma unroll
            for (int nt = 0; nt < 12; ++nt)
#pragma unroll
                for (int i = 0; i < 4; ++i) acc[mt][nt][i] = 0.f;

        // prefetch X chunk 0 of this half
        float4 xp[8];
#pragma unroll
        for (int i = 0; i < 8; ++i) {
            int idx = tid + (i << 8);
            xp[i] = *reinterpret_cast<const float4*>(
                gx + (idx >> 4) * CDIM + ((idx & 15) << 2));
        }

        for (int ch = 0; ch < 6; ++ch) {
            const int buf = ch & 1;
            // ---- store prefetched X chunk (f32 -> fp16, swizzled) ------------
#pragma unroll
            for (int i = 0; i < 8; ++i) {
                int idx = tid + (i << 8);
                int row = idx >> 4, f4 = idx & 15;
                float4 v = xp[i];
                *reinterpret_cast<uint2*>(sm + FX(buf) + swz128(row, f4 << 3)) =
                    make_uint2(pkh(v.x, v.y), pkh(v.z, v.w));
            }
            // ---- stage W chunk (raw uint4 copy of preconverted fp16) ---------
            {
                const int slab = ch * 24576;
#pragma unroll
                for (int i = 0; i < 6; ++i) {
                    int boff = (tid + (i << 8)) << 4;
                    *reinterpret_cast<uint4*>(sm + FW(buf) + boff) =
                        *reinterpret_cast<const uint4*>(gw + slab + boff);
                }
            }
            __syncthreads();
            // ---- prefetch next X chunk ---------------------------------------
            if (ch < 5) {
                const int kc = (ch + 1) * KC;
#pragma unroll
                for (int i = 0; i < 8; ++i) {
                    int idx = tid + (i << 8);
                    xp[i] = *reinterpret_cast<const float4*>(
                        gx + (idx >> 4) * CDIM + kc + ((idx & 15) << 2));
                }
            }
            // ---- mma: single fp16 chain ---------------------------------------
#pragma unroll
            for (int ks = 0; ks < 4; ++ks) {
                uint32_t ah[2][4];
                int arow  = (wm << 5) + (lane & 15);
                int abyte = ((ks << 1) + (lane >> 4)) << 4;
                ldsm4(ah[0], smb + FX(buf) + swz128(arow,      abyte));
                ldsm4(ah[1], smb + FX(buf) + swz128(arow + 16, abyte));
                int krow = (ks << 4) + (lane & 15);
#pragma unroll
                for (int j = 0; j < 6; ++j) {
                    const int n0 = 2 * j;
                    const int ntg = wn * 12 + n0;
                    uint32_t bh[4];
                    ldsm4t(bh, smb + FW(buf) + swzW(krow, (ntg + (lane >> 4)) << 4));
                    mma16816(acc[0][n0],     ah[0], bh[0], bh[1]);
                    mma16816(acc[1][n0],     ah[1], bh[0], bh[1]);
                    mma16816(acc[0][n0 + 1], ah[0], bh[2], bh[3]);
                    mma16816(acc[1][n0 + 1], ah[1], bh[2], bh[3]);
                }
            }
        }

        // ---- epilogue: Q scaled by eta; write fp16 into attn smem layout -----
#pragma unroll
        for (int mt = 0; mt < 2; ++mt) {
#pragma unroll
            for (int ntl = 0; ntl < 12; ++ntl) {
                const int ntg = wn * 12 + ntl;
#pragma unroll
                for (int r = 0; r < 2; ++r) {
                    float p0 = acc[mt][ntl][2 * r], p1 = acc[mt][ntl][2 * r + 1];
                    if (ntg < 8) { p0 *= eta; p1 *= eta; }
                    int row = rhalf + (wm << 5) + (mt << 4) + g + (r << 3);
                    int sec = ntg >> 3;                    // 0=Q 1=K 2=V
                    int off = swz128(row, ((ntg & 7) << 4) + (t2 << 1));
                    *reinterpret_cast<uint32_t*>(sm + sec * 32768 + off) = pkh(p0, p1);
                }
            }
        }
    }
    __syncthreads();   // QKV smem complete, staging buffers now dead

    // ===================== Phase 2: balanced causal flash attention ==========
    const int rbase0 = w << 4,  rbase1 = (15 - w) << 4;
    const int jmax0  = w >> 2,  jmax1  = (15 - w) >> 2;    // jmax1 >= jmax0

    float O[2][8][4];
#pragma unroll
    for (int mt = 0; mt < 2; ++mt)
#pragma unroll
        for (int nt = 0; nt < 8; ++nt)
#pragma unroll
            for (int i = 0; i < 4; ++i) O[mt][nt][i] = 0.f;
    float mrow[2][2] = {{-1e30f, -1e30f}, {-1e30f, -1e30f}};
    float lrow[2][2] = {{0.f, 0.f}, {0.f, 0.f}};

    for (int jt = 0; jt <= jmax1; ++jt) {
        const bool act0 = (jt <= jmax0);
        float S[2][8][4];
#pragma unroll
        for (int mt = 0; mt < 2; ++mt)
#pragma unroll
            for (int nt = 0; nt < 8; ++nt)
#pragma unroll
                for (int i = 0; i < 4; ++i) S[mt][nt][i] = 0.f;

        // ---- S = Q K^T ---------------------------------------------------------
#pragma unroll
        for (int ks = 0; ks < 4; ++ks) {
            uint32_t qh[2][4];
            int abyte = ((ks << 1) + (lane >> 4)) << 4;
            int lrow16 = lane & 15;
            if (act0) ldsm4(qh[0], smb + FQ + swz128(rbase0 + lrow16, abyte));
            ldsm4(qh[1], smb + FQ + swz128(rbase1 + lrow16, abyte));
            int kr    = (jt << 6) + (lane & 7);
            int kbyte = ((ks << 1) + ((lane >> 3) & 1)) << 4;
#pragma unroll
            for (int nt = 0; nt < 8; ++nt) {
                uint32_t b0, b1;
                ldsm2(b0, b1, smb + FK + swz128(kr + (nt << 3), kbyte));
                if (act0) mma16816(S[0][nt], qh[0], b0, b1);
                mma16816(S[1][nt], qh[1], b0, b1);
            }
        }
        // ---- causal mask on each block's diagonal tile ---------------------------
#pragma unroll
        for (int mt = 0; mt < 2; ++mt) {
            const int jm = (mt == 0) ? jmax0 : jmax1;
            const int rb = (mt == 0) ? rbase0 : rbase1;
            if (jt == jm) {
#pragma unroll
                for (int nt = 0; nt < 8; ++nt)
#pragma unroll
                    for (int r = 0; r < 2; ++r)
#pragma unroll
                        for (int cc = 0; cc < 2; ++cc) {
                            int col = (jt << 6) + (nt << 3) + t2 + cc;
                            int row = rb + g + (r << 3);
                            if (col > row) S[mt][nt][2 * r + cc] = -1e30f;
                        }
            }
        }
        // ---- online softmax (active blocks only) ---------------------------------
#pragma unroll
        for (int mt = 0; mt < 2; ++mt) {
            if (mt == 0 && !act0) continue;
#pragma unroll
            for (int r = 0; r < 2; ++r) {
                float vmax = -1e30f;
#pragma unroll
                for (int nt = 0; nt < 8; ++nt)
                    vmax = fmaxf(vmax, fmaxf(S[mt][nt][2 * r], S[mt][nt][2 * r + 1]));
                vmax = fmaxf(vmax, __shfl_xor_sync(0xffffffffu, vmax, 1));
                vmax = fmaxf(vmax, __shfl_xor_sync(0xffffffffu, vmax, 2));
                float mnew  = fmaxf(mrow[mt][r], vmax);
                float alpha = ex2(mrow[mt][r] - mnew);
                mrow[mt][r] = mnew;
                float ls = 0.f;
#pragma unroll
                for (int nt = 0; nt < 8; ++nt) {
                    float p0 = ex2(S[mt][nt][2 * r]     - mnew);
                    float p1 = ex2(S[mt][nt][2 * r + 1] - mnew);
                    S[mt][nt][2 * r] = p0; S[mt][nt][2 * r + 1] = p1;
                    ls += p0 + p1;
                }
                lrow[mt][r] = lrow[mt][r] * alpha + ls;
#pragma unroll
                for (int nt = 0; nt < 8; ++nt) {
                    O[mt][nt][2 * r]     *= alpha;
                    O[mt][nt][2 * r + 1] *= alpha;
                }
            }
        }
        // ---- O += P V (active blocks only) ----------------------------------------
#pragma unroll
        for (int ks = 0; ks < 4; ++ks) {
            uint32_t ph[2][4];
#pragma unroll
            for (int mt = 0; mt < 2; ++mt) {
                if (mt == 0 && !act0) continue;
                ph[mt][0] = pkh(S[mt][2 * ks][0],     S[mt][2 * ks][1]);
                ph[mt][1] = pkh(S[mt][2 * ks][2],     S[mt][2 * ks][3]);
                ph[mt][2] = pkh(S[mt][2 * ks + 1][0], S[mt][2 * ks + 1][1]);
                ph[mt][3] = pkh(S[mt][2 * ks + 1][2], S[mt][2 * ks + 1][3]);
            }
            int vr = (jt << 6) + (ks << 4) + (lane & 15);
#pragma unroll
            for (int nt = 0; nt < 8; ++nt) {
                uint32_t b0, b1;
                ldsm2t(b0, b1, smb + FV + swz128(vr, nt << 4));
                if (act0) mma16816(O[0][nt], ph[0], b0, b1);
                mma16816(O[1][nt], ph[1], b0, b1);
            }
        }
    }

    // ---- finalize + store --------------------------------------------------------
#pragma unroll
    for (int mt = 0; mt < 2; ++mt) {
        const int rb = (mt == 0) ? rbase0 : rbase1;
#pragma unroll
        for (int r = 0; r < 2; ++r) {
            float lt = lrow[mt][r];
            lt += __shfl_xor_sync(0xffffffffu, lt, 1);
            lt += __shfl_xor_sync(0xffffffffu, lt, 2);
            float inv = __frcp_rn(lt);
            int row = rb + g + (r << 3);
            float* op = out + ((size_t)blockIdx.x * TSEQ + row) * HDIM;
#pragma unroll
            for (int nt = 0; nt < 8; ++nt) {
                float2 v = make_float2(O[mt][nt][2 * r] * inv, O[mt][nt][2 * r + 1] * inv);
                *reinterpret_cast<float2*>(op + (nt << 3) + t2) = v;
            }
        }
    }
}

// ---- launch -----------------------------------------------------------------
extern "C" void kernel_launch(void* const* d_in, const int* in_sizes, int n_in,
                              void* d_out, int out_size)
{
    const float* x  = (const float*)d_in[0];
    const float* Wq = (const float*)d_in[1];
    const float* Wk = (const float*)d_in[2];
    const float* Wv = (const float*)d_in[3];
    float* out = (float*)d_out;

    int B = in_sizes[0] / (TSEQ * CDIM);          // 1024

    cudaFuncSetAttribute(head_kernel, cudaFuncAttributeMaxDynamicSharedMemorySize, FSMEM);

    prep_w<<<(CDIM * NDIM + 255) / 256, 256>>>(Wq, Wk, Wv);
    head_kernel<<<B, 256, FSMEM>>>(x, out);
}

// round 16
// speedup vs baseline: 1.1419x; 1.0399x over previous
#include <cuda_runtime.h>
#include <cuda_fp16.h>
#include <math.h>
#include <stdint.h>

#define BATCH 1024
#define TSEQ  256
#define CDIM  384
#define HDIM  64
#define NDIM  192
#define KC    64

// ---- global scratch: pre-swizzled fp16 W ------------------------------------
__device__ __align__(16) __half gW[CDIM * NDIM];

// ---- helpers ----------------------------------------------------------------
__device__ __forceinline__ uint32_t smem_u32(const void* p) {
    uint32_t a;
    asm("{ .reg .u64 t; cvta.to.shared.u64 t, %1; cvt.u32.u64 %0, t; }" : "=r"(a) : "l"(p));
    return a;
}
// 128B-row tile swizzle (8 16B atoms per row)
__device__ __forceinline__ int swz128(int row, int byteoff) {
    return row * 128 + ((((byteoff >> 4) ^ row) & 7) << 4) + (byteoff & 15);
}
// W tile: 384B rows (24 atoms), swizzle within 8-atom groups
__device__ __forceinline__ int swzW(int k, int byteoff) {
    int atom = byteoff >> 4;
    return k * 384 + (((atom & ~7) | ((atom ^ k) & 7)) << 4) + (byteoff & 15);
}
__device__ __forceinline__ uint32_t pkh(float lo, float hi) {   // f16x2 {hi|lo}
    uint32_t r; asm("cvt.rn.f16x2.f32 %0, %1, %2;" : "=r"(r) : "f"(hi), "f"(lo)); return r;
}
__device__ __forceinline__ float ex2(float x) {
    float y; asm("ex2.approx.ftz.f32 %0, %1;" : "=f"(y) : "f"(x)); return y;
}
__device__ __forceinline__ void ldsm4(uint32_t* r, uint32_t a) {
    asm volatile("ldmatrix.sync.aligned.m8n8.x4.shared.b16 {%0,%1,%2,%3}, [%4];"
                 : "=r"(r[0]), "=r"(r[1]), "=r"(r[2]), "=r"(r[3]) : "r"(a));
}
__device__ __forceinline__ void ldsm4t(uint32_t* r, uint32_t a) {
    asm volatile("ldmatrix.sync.aligned.m8n8.x4.trans.shared.b16 {%0,%1,%2,%3}, [%4];"
                 : "=r"(r[0]), "=r"(r[1]), "=r"(r[2]), "=r"(r[3]) : "r"(a));
}
__device__ __forceinline__ void mma16816(float* c, const uint32_t* a,
                                         uint32_t b0, uint32_t b1) {
    asm volatile("mma.sync.aligned.m16n8k16.row.col.f32.f16.f16.f32 "
                 "{%0,%1,%2,%3}, {%4,%5,%6,%7}, {%8,%9}, {%0,%1,%2,%3};"
                 : "+f"(c[0]), "+f"(c[1]), "+f"(c[2]), "+f"(c[3])
                 : "r"(a[0]), "r"(a[1]), "r"(a[2]), "r"(a[3]), "r"(b0), "r"(b1));
}

// ============================================================================
// Kernel 0: pre-convert W -> fp16, pre-swizzled [384k x 192n] layout.
// ============================================================================
__global__ void prep_w(const float* __restrict__ Wq, const float* __restrict__ Wk,
                       const float* __restrict__ Wv) {
    int idx = blockIdx.x * 256 + threadIdx.x;      // over 384*192
    if (idx >= CDIM * NDIM) return;
    int k = idx / NDIM, n = idx % NDIM;
    const float* Wp = (n < 64) ? Wq : (n < 128) ? Wk : Wv;
    float v = Wp[k * HDIM + (n & 63)];
    *reinterpret_cast<__half*>(reinterpret_cast<char*>(gW) + swzW(k, 2 * n)) =
        __float2half_rn(v);
}

// ============================================================================
// Fused kernel: QKV projection (2 half-passes) + causal flash attention.
// grid = 1024 (one CTA per batch), 256 thr.
// smem: Q 32KB | K 32KB | V 32KB | X dbuf 2x16KB | W dbuf 2x24KB = 176KB
// ============================================================================
#define FQ 0
#define FK 32768
#define FV 65536
#define FX(buf) (98304  + (buf) * 16384)
#define FW(buf) (131072 + (buf) * 24576)
#define FSMEM 180224

__global__ void __launch_bounds__(256, 1)
head_kernel(const float* __restrict__ x, float* __restrict__ out)
{
    extern __shared__ char sm[];
    const uint32_t smb = smem_u32(sm);
    const int tid = threadIdx.x, lane = tid & 31, w = tid >> 5;
    const int wm = w & 3, wn = w >> 2;
    const int g = lane >> 2, t2 = (lane & 3) << 1;
    const char* gw = reinterpret_cast<const char*>(gW);
    const float eta = 1.44269504088896340736f * rsqrtf((float)CDIM);

    // ===================== Phase 1: QKV -> smem (2 half-passes) ==============
    for (int half = 0; half < 2; ++half) {
        const int rhalf = half << 7;                       // 0 or 128
        const float* gx = x + ((size_t)blockIdx.x * TSEQ + rhalf) * CDIM;

        float acc[2][12][4];
#pragma unroll
        for (int mt = 0; mt < 2; ++mt)
#pragma unroll
            for (int nt = 0; nt < 12; ++nt)
#pragma unroll
                for (int i = 0; i < 4; ++i) acc[mt][nt][i] = 0.f;

        // prefetch X chunk 0 of this half
        float4 xp[8];
#pragma unroll
        for (int i = 0; i < 8; ++i) {
            int idx = tid + (i << 8);
            xp[i] = *reinterpret_cast<const float4*>(
                gx + (idx >> 4) * CDIM + ((idx & 15) << 2));
        }

        for (int ch = 0; ch < 6; ++ch) {
            const int buf = ch & 1;
            // ---- store prefetched X chunk (f32 -> fp16, swizzled) ------------
#pragma unroll
            for (int i = 0; i < 8; ++i) {
                int idx = tid + (i << 8);
                int row = idx >> 4, f4 = idx & 15;
                float4 v = xp[i];
                *reinterpret_cast<uint2*>(sm + FX(buf) + swz128(row, f4 << 3)) =
                    make_uint2(pkh(v.x, v.y), pkh(v.z, v.w));
            }
            // ---- stage W chunk (raw uint4 copy of preconverted fp16) ---------
            {
                const int slab = ch * 24576;
#pragma unroll
                for (int i = 0; i < 6; ++i) {
                    int boff = (tid + (i << 8)) << 4;
                    *reinterpret_cast<uint4*>(sm + FW(buf) + boff) =
                        *reinterpret_cast<const uint4*>(gw + slab + boff);
                }
            }
            __syncthreads();
            // ---- prefetch next X chunk ---------------------------------------
            if (ch < 5) {
                const int kc = (ch + 1) * KC;
#pragma unroll
                for (int i = 0; i < 8; ++i) {
                    int idx = tid + (i << 8);
                    xp[i] = *reinterpret_cast<const float4*>(
                        gx + (idx >> 4) * CDIM + kc + ((idx & 15) << 2));
                }
            }
            // ---- mma: single fp16 chain ---------------------------------------
#pragma unroll
            for (int ks = 0; ks < 4; ++ks) {
                uint32_t ah[2][4];
                int arow  = (wm << 5) + (lane & 15);
                int abyte = ((ks << 1) + (lane >> 4)) << 4;
                ldsm4(ah[0], smb + FX(buf) + swz128(arow,      abyte));
                ldsm4(ah[1], smb + FX(buf) + swz128(arow + 16, abyte));
                int krow = (ks << 4) + (lane & 15);
#pragma unroll
                for (int j = 0; j < 6; ++j) {
                    const int n0 = 2 * j;
                    const int ntg = wn * 12 + n0;
                    uint32_t bh[4];
                    ldsm4t(bh, smb + FW(buf) + swzW(krow, (ntg + (lane >> 4)) << 4));
                    mma16816(acc[0][n0],     ah[0], bh[0], bh[1]);
                    mma16816(acc[1][n0],     ah[1], bh[0], bh[1]);
                    mma16816(acc[0][n0 + 1], ah[0], bh[2], bh[3]);
                    mma16816(acc[1][n0 + 1], ah[1], bh[2], bh[3]);
                }
            }
        }

        // ---- epilogue: Q scaled by eta; write fp16 into attn smem layout -----
#pragma unroll
        for (int mt = 0; mt < 2; ++mt) {
#pragma unroll
            for (int ntl = 0; ntl < 12; ++ntl) {
                const int ntg = wn * 12 + ntl;
#pragma unroll
                for (int r = 0; r < 2; ++r) {
                    float p0 = acc[mt][ntl][2 * r], p1 = acc[mt][ntl][2 * r + 1];
                    if (ntg < 8) { p0 *= eta; p1 *= eta; }
                    int row = rhalf + (wm << 5) + (mt << 4) + g + (r << 3);
                    int sec = ntg >> 3;                    // 0=Q 1=K 2=V
                    int off = swz128(row, ((ntg & 7) << 4) + (t2 << 1));
                    *reinterpret_cast<uint32_t*>(sm + sec * 32768 + off) = pkh(p0, p1);
                }
            }
        }
    }
    __syncthreads();   // QKV smem complete, staging buffers now dead

    // ===================== Phase 2: balanced causal flash attention ==========
    const int rbase0 = w << 4,  rbase1 = (15 - w) << 4;
    const int jmax0  = w >> 2,  jmax1  = (15 - w) >> 2;    // jmax1 >= jmax0

    float O[2][8][4];
#pragma unroll
    for (int mt = 0; mt < 2; ++mt)
#pragma unroll
        for (int nt = 0; nt < 8; ++nt)
#pragma unroll
            for (int i = 0; i < 4; ++i) O[mt][nt][i] = 0.f;
    float mrow[2][2] = {{-1e30f, -1e30f}, {-1e30f, -1e30f}};
    float lrow[2][2] = {{0.f, 0.f}, {0.f, 0.f}};

    for (int jt = 0; jt <= jmax1; ++jt) {
        const bool act0 = (jt <= jmax0);
        float S[2][8][4];
#pragma unroll
        for (int mt = 0; mt < 2; ++mt)
#pragma unroll
            for (int nt = 0; nt < 8; ++nt)
#pragma unroll
                for (int i = 0; i < 4; ++i) S[mt][nt][i] = 0.f;

        // ---- S = Q K^T (x4 K-loads: two n-tiles per ldmatrix) -----------------
#pragma unroll
        for (int ks = 0; ks < 4; ++ks) {
            uint32_t qh[2][4];
            int abyte = ((ks << 1) + (lane >> 4)) << 4;
            int lrow16 = lane & 15;
            if (act0) ldsm4(qh[0], smb + FQ + swz128(rbase0 + lrow16, abyte));
            ldsm4(qh[1], smb + FQ + swz128(rbase1 + lrow16, abyte));
            // lanes 0-15 -> n-tile nt, lanes 16-31 -> n-tile nt+1;
            // within each half: lanes 0-7 atom 2ks, 8-15 atom 2ks+1 (as before)
            int kr    = (jt << 6) + (lane & 7) + ((lane >> 4) << 3);   // +8 rows for hi half? no:
            // NOTE: row = (lane&7) within the addressed matrix; matrix chosen by octet.
            kr = (jt << 6) + (lane & 7);
            int kbyte = ((ks << 1) + ((lane >> 3) & 1)) << 4;
#pragma unroll
            for (int nt = 0; nt < 8; nt += 2) {
                uint32_t b[4];
                int ntl = nt + (lane >> 4);                 // second octet pair -> nt+1
                ldsm4(b, smb + FK + swz128(kr + (ntl << 3), kbyte));
                if (act0) {
                    mma16816(S[0][nt],     qh[0], b[0], b[1]);
                    mma16816(S[0][nt + 1], qh[0], b[2], b[3]);
                }
                mma16816(S[1][nt],     qh[1], b[0], b[1]);
                mma16816(S[1][nt + 1], qh[1], b[2], b[3]);
            }
        }
        // ---- causal mask on each block's diagonal tile ---------------------------
#pragma unroll
        for (int mt = 0; mt < 2; ++mt) {
            const int jm = (mt == 0) ? jmax0 : jmax1;
            const int rb = (mt == 0) ? rbase0 : rbase1;
            if (jt == jm) {
#pragma unroll
                for (int nt = 0; nt < 8; ++nt)
#pragma unroll
                    for (int r = 0; r < 2; ++r)
#pragma unroll
                        for (int cc = 0; cc < 2; ++cc) {
                            int col = (jt << 6) + (nt << 3) + t2 + cc;
                            int row = rb + g + (r << 3);
                            if (col > row) S[mt][nt][2 * r + cc] = -1e30f;
                        }
            }
        }
        // ---- online softmax (active blocks only) ---------------------------------
#pragma unroll
        for (int mt = 0; mt < 2; ++mt) {
            if (mt == 0 && !act0) continue;
#pragma unroll
            for (int r = 0; r < 2; ++r) {
                float vmax = -1e30f;
#pragma unroll
                for (int nt = 0; nt < 8; ++nt)
                    vmax = fmaxf(vmax, fmaxf(S[mt][nt][2 * r], S[mt][nt][2 * r + 1]));
                vmax = fmaxf(vmax, __shfl_xor_sync(0xffffffffu, vmax, 1));
                vmax = fmaxf(vmax, __shfl_xor_sync(0xffffffffu, vmax, 2));
                float mnew  = fmaxf(mrow[mt][r], vmax);
                float alpha = ex2(mrow[mt][r] - mnew);
                mrow[mt][r] = mnew;
                float ls = 0.f;
#pragma unroll
                for (int nt = 0; nt < 8; ++nt) {
                    float p0 = ex2(S[mt][nt][2 * r]     - mnew);
                    float p1 = ex2(S[mt][nt][2 * r + 1] - mnew);
                    S[mt][nt][2 * r] = p0; S[mt][nt][2 * r + 1] = p1;
                    ls += p0 + p1;
                }
                lrow[mt][r] = lrow[mt][r] * alpha + ls;
#pragma unroll
                for (int nt = 0; nt < 8; ++nt) {
                    O[mt][nt][2 * r]     *= alpha;
                    O[mt][nt][2 * r + 1] *= alpha;
                }
            }
        }
        // ---- O += P V (x4t V-loads: two n-tiles per ldmatrix) ---------------------
#pragma unroll
        for (int ks = 0; ks < 4; ++ks) {
            uint32_t ph[2][4];
#pragma unroll
            for (int mt = 0; mt < 2; ++mt) {
                if (mt == 0 && !act0) continue;
                ph[mt][0] = pkh(S[mt][2 * ks][0],     S[mt][2 * ks][1]);
                ph[mt][1] = pkh(S[mt][2 * ks][2],     S[mt][2 * ks][3]);
                ph[mt][2] = pkh(S[mt][2 * ks + 1][0], S[mt][2 * ks + 1][1]);
                ph[mt][3] = pkh(S[mt][2 * ks + 1][2], S[mt][2 * ks + 1][3]);
            }
            int vr = (jt << 6) + (ks << 4) + (lane & 15);
#pragma unroll
            for (int nt = 0; nt < 8; nt += 2) {
                uint32_t b[4];
                int ntl = nt + (lane >> 4);                 // lanes 16-31 -> nt+1 col block
                ldsm4t(b, smb + FV + swz128(vr, ntl << 4));
                if (act0) {
                    mma16816(O[0][nt],     ph[0], b[0], b[1]);
                    mma16816(O[0][nt + 1], ph[0], b[2], b[3]);
                }
                mma16816(O[1][nt],     ph[1], b[0], b[1]);
                mma16816(O[1][nt + 1], ph[1], b[2], b[3]);
            }
        }
    }

    // ---- finalize + store --------------------------------------------------------
#pragma unroll
    for (int mt = 0; mt < 2; ++mt) {
        const int rb = (mt == 0) ? rbase0 : rbase1;
#pragma unroll
        for (int r = 0; r < 2; ++r) {
            float lt = lrow[mt][r];
            lt += __shfl_xor_sync(0xffffffffu, lt, 1);
            lt += __shfl_xor_sync(0xffffffffu, lt, 2);
            float inv = __frcp_rn(lt);
            int row = rb + g + (r << 3);
            float* op = out + ((size_t)blockIdx.x * TSEQ + row) * HDIM;
#pragma unroll
            for (int nt = 0; nt < 8; ++nt) {
                float2 v = make_float2(O[mt][nt][2 * r] * inv, O[mt][nt][2 * r + 1] * inv);
                *reinterpret_cast<float2*>(op + (nt << 3) + t2) = v;
            }
        }
    }
}

// ---- launch -----------------------------------------------------------------
extern "C" void kernel_launch(void* const* d_in, const int* in_sizes, int n_in,
                              void* d_out, int out_size)
{
    const float* x  = (const float*)d_in[0];
    const float* Wq = (const float*)d_in[1];
    const float* Wk = (const float*)d_in[2];
    const float* Wv = (const float*)d_in[3];
    float* out = (float*)d_out;

    int B = in_sizes[0] / (TSEQ * CDIM);          // 1024

    cudaFuncSetAttribute(head_kernel, cudaFuncAttributeMaxDynamicSharedMemorySize, FSMEM);

    prep_w<<<(CDIM * NDIM + 255) / 256, 256>>>(Wq, Wk, Wv);
    head_kernel<<<B, 256, FSMEM>>>(x, out);
}